// round 1
// baseline (speedup 1.0000x reference)
#include <cuda_runtime.h>
#include <math.h>

#define N_NODES 100000
#define N_EDGES 20000
#define NNZ     1600000
#define D       128

// ---------------- scratch (device globals: allocation-free rule) ----------------
__device__ int   g_cnt_v[N_NODES];
__device__ int   g_cnt_e[N_EDGES];
__device__ int   g_offs_v[N_NODES + 1];
__device__ int   g_offs_e[N_EDGES + 1];
__device__ int   g_cur_v[N_NODES];
__device__ int   g_cur_e[N_EDGES];
__device__ float g_inv_sqrt_dv[N_NODES];
__device__ float g_inv_de[N_EDGES];
__device__ int   g_edge_adj[NNZ];   // per-edge list of vertex ids
__device__ int   g_node_adj[NNZ];   // per-node list of edge ids
__device__ float g_Xs[(size_t)N_NODES * D];   // (X@W + b) * dv^-1/2
__device__ float g_Ye[(size_t)N_EDGES * D];   // edge aggregates * de^-1

// ---------------- 0: zero counters ----------------
__global__ void zero_counts_kernel() {
    int i = blockIdx.x * blockDim.x + threadIdx.x;
    if (i < N_NODES) g_cnt_v[i] = 0;
    if (i < N_EDGES) g_cnt_e[i] = 0;
}

// ---------------- 1: degree histograms ----------------
__global__ void degree_kernel(const int* __restrict__ v_idx, const int* __restrict__ e_idx) {
    int i = blockIdx.x * blockDim.x + threadIdx.x;
    if (i < NNZ) {
        atomicAdd(&g_cnt_v[v_idx[i]], 1);
        atomicAdd(&g_cnt_e[e_idx[i]], 1);
    }
}

// ---------------- 2: single-block exclusive scan (chunked, shfl-based) ----------------
__global__ void scan_kernel(const int* __restrict__ in, int n, int* __restrict__ out) {
    __shared__ int wsum[32];
    __shared__ int carry_s;
    int tid = threadIdx.x;           // 1024 threads
    if (tid == 0) carry_s = 0;
    __syncthreads();
    for (int base = 0; base < n; base += 1024) {
        int i = base + tid;
        int x = (i < n) ? in[i] : 0;
        // warp inclusive scan
        int v = x;
        #pragma unroll
        for (int o = 1; o < 32; o <<= 1) {
            int t = __shfl_up_sync(0xFFFFFFFFu, v, o);
            if ((tid & 31) >= o) v += t;
        }
        if ((tid & 31) == 31) wsum[tid >> 5] = v;
        __syncthreads();
        if (tid < 32) {
            int w = wsum[tid];
            #pragma unroll
            for (int o = 1; o < 32; o <<= 1) {
                int t = __shfl_up_sync(0xFFFFFFFFu, w, o);
                if (tid >= o) w += t;
            }
            wsum[tid] = w;
        }
        __syncthreads();
        int warppre = (tid >= 32) ? wsum[(tid >> 5) - 1] : 0;
        int incl = v + warppre + carry_s;
        if (i < n) out[i] = incl - x;   // exclusive
        __syncthreads();                // everyone read carry_s
        if (tid == 1023) carry_s = incl;
        __syncthreads();
    }
    if (tid == 0) out[n] = carry_s;
}

// ---------------- 3: inverse degree factors + cursor init ----------------
__global__ void init_kernel() {
    int i = blockIdx.x * blockDim.x + threadIdx.x;
    if (i < N_NODES) {
        int c = g_cnt_v[i];
        g_inv_sqrt_dv[i] = (c > 0) ? rsqrtf((float)c) : 0.0f;
        g_cur_v[i] = g_offs_v[i];
    }
    if (i < N_EDGES) {
        int c = g_cnt_e[i];
        g_inv_de[i] = (c > 0) ? (1.0f / (float)c) : 0.0f;
        g_cur_e[i] = g_offs_e[i];
    }
}

// ---------------- 4: CSR fill (both directions) ----------------
__global__ void fill_kernel(const int* __restrict__ v_idx, const int* __restrict__ e_idx) {
    int i = blockIdx.x * blockDim.x + threadIdx.x;
    if (i < NNZ) {
        int v = v_idx[i];
        int e = e_idx[i];
        int pe = atomicAdd(&g_cur_e[e], 1);
        g_edge_adj[pe] = v;
        int pv = atomicAdd(&g_cur_v[v], 1);
        g_node_adj[pv] = e;
    }
}

// ---------------- 5: GEMM  Xs = (X @ W + b) * inv_sqrt_dv ----------------
#define BM 64
#define XS_STRIDE 132
#define GEMM_SMEM_BYTES ((128 * 128 + BM * XS_STRIDE + 128) * 4)

__global__ void __launch_bounds__(256, 2)
gemm_kernel(const float* __restrict__ X, const float* __restrict__ W,
            const float* __restrict__ bias) {
    extern __shared__ float sm[];
    float* Wsm = sm;                       // [128][128]
    float* Xsm = sm + 128 * 128;           // [BM][XS_STRIDE]
    float* bsm = Xsm + BM * XS_STRIDE;     // [128]

    int tid = threadIdx.x;                 // 256
    int row0 = blockIdx.x * BM;

    // load W (row-major [k][n])
    for (int i = tid; i < 128 * 32; i += 256)
        ((float4*)Wsm)[i] = ((const float4*)W)[i];
    if (tid < 32)
        ((float4*)bsm)[tid] = ((const float4*)bias)[tid];
    // load X tile [BM][128], row-major with pad
    for (int i = tid; i < BM * 32; i += 256) {
        int m = i >> 5, kq = i & 31;
        int gr = row0 + m;
        float4 vv = (gr < N_NODES) ? ((const float4*)(X + (size_t)gr * D))[kq]
                                   : make_float4(0.f, 0.f, 0.f, 0.f);
        *((float4*)(Xsm + m * XS_STRIDE + kq * 4)) = vv;
    }
    __syncthreads();

    int tx = tid & 31;     // col group: c0 = tx*4
    int ty = tid >> 5;     // row group: r0 = ty*8
    int c0 = tx * 4, r0 = ty * 8;

    float acc[8][4];
    #pragma unroll
    for (int j = 0; j < 8; j++) {
        acc[j][0] = 0.f; acc[j][1] = 0.f; acc[j][2] = 0.f; acc[j][3] = 0.f;
    }

    #pragma unroll 8
    for (int k = 0; k < 128; k++) {
        float4 b4 = *(const float4*)(Wsm + k * 128 + c0);
        #pragma unroll
        for (int j = 0; j < 8; j++) {
            float a = Xsm[(r0 + j) * XS_STRIDE + k];  // warp-broadcast
            acc[j][0] = fmaf(a, b4.x, acc[j][0]);
            acc[j][1] = fmaf(a, b4.y, acc[j][1]);
            acc[j][2] = fmaf(a, b4.z, acc[j][2]);
            acc[j][3] = fmaf(a, b4.w, acc[j][3]);
        }
    }

    float4 bb = *(const float4*)(bsm + c0);
    #pragma unroll
    for (int j = 0; j < 8; j++) {
        int gr = row0 + r0 + j;
        if (gr < N_NODES) {
            float s = g_inv_sqrt_dv[gr];
            float4 o;
            o.x = (acc[j][0] + bb.x) * s;
            o.y = (acc[j][1] + bb.y) * s;
            o.z = (acc[j][2] + bb.z) * s;
            o.w = (acc[j][3] + bb.w) * s;
            ((float4*)(g_Xs + (size_t)gr * D))[tx] = o;
        }
    }
}

// ---------------- 6: edge gather-reduce  Ye[e] = inv_de[e] * sum_{v in e} Xs[v] ----------------
__global__ void edge_reduce_kernel() {
    int gw = (blockIdx.x * blockDim.x + threadIdx.x) >> 5;
    if (gw >= N_EDGES) return;
    int lane = threadIdx.x & 31;
    int beg = g_offs_e[gw], end = g_offs_e[gw + 1];
    const float4* Xs4 = (const float4*)g_Xs;
    float sx = 0.f, sy = 0.f, sz = 0.f, sw = 0.f;
    int j = beg;
    for (; j + 4 <= end; j += 4) {
        int v0 = g_edge_adj[j + 0];
        int v1 = g_edge_adj[j + 1];
        int v2 = g_edge_adj[j + 2];
        int v3 = g_edge_adj[j + 3];
        float4 p0 = Xs4[(size_t)v0 * 32 + lane];
        float4 p1 = Xs4[(size_t)v1 * 32 + lane];
        float4 p2 = Xs4[(size_t)v2 * 32 + lane];
        float4 p3 = Xs4[(size_t)v3 * 32 + lane];
        sx += p0.x + p1.x + p2.x + p3.x;
        sy += p0.y + p1.y + p2.y + p3.y;
        sz += p0.z + p1.z + p2.z + p3.z;
        sw += p0.w + p1.w + p2.w + p3.w;
    }
    for (; j < end; j++) {
        int v = g_edge_adj[j];
        float4 p = Xs4[(size_t)v * 32 + lane];
        sx += p.x; sy += p.y; sz += p.z; sw += p.w;
    }
    float s = g_inv_de[gw];
    ((float4*)g_Ye)[(size_t)gw * 32 + lane] = make_float4(sx * s, sy * s, sz * s, sw * s);
}

// ---------------- 7: node gather-reduce  out[v] = relu(inv_sqrt_dv[v] * sum_{e ni v} Ye[e]) ----------------
__global__ void node_reduce_kernel(float* __restrict__ out) {
    int gw = (blockIdx.x * blockDim.x + threadIdx.x) >> 5;
    if (gw >= N_NODES) return;
    int lane = threadIdx.x & 31;
    int beg = g_offs_v[gw], end = g_offs_v[gw + 1];
    const float4* Ye4 = (const float4*)g_Ye;
    float sx = 0.f, sy = 0.f, sz = 0.f, sw = 0.f;
    int j = beg;
    for (; j + 4 <= end; j += 4) {
        int e0 = g_node_adj[j + 0];
        int e1 = g_node_adj[j + 1];
        int e2 = g_node_adj[j + 2];
        int e3 = g_node_adj[j + 3];
        float4 p0 = Ye4[(size_t)e0 * 32 + lane];
        float4 p1 = Ye4[(size_t)e1 * 32 + lane];
        float4 p2 = Ye4[(size_t)e2 * 32 + lane];
        float4 p3 = Ye4[(size_t)e3 * 32 + lane];
        sx += p0.x + p1.x + p2.x + p3.x;
        sy += p0.y + p1.y + p2.y + p3.y;
        sz += p0.z + p1.z + p2.z + p3.z;
        sw += p0.w + p1.w + p2.w + p3.w;
    }
    for (; j < end; j++) {
        int e = g_node_adj[j];
        float4 p = Ye4[(size_t)e * 32 + lane];
        sx += p.x; sy += p.y; sz += p.z; sw += p.w;
    }
    float s = g_inv_sqrt_dv[gw];
    float4 o;
    o.x = fmaxf(sx * s, 0.f);
    o.y = fmaxf(sy * s, 0.f);
    o.z = fmaxf(sz * s, 0.f);
    o.w = fmaxf(sw * s, 0.f);
    ((float4*)out)[(size_t)gw * 32 + lane] = o;
}

// ---------------- launch ----------------
extern "C" void kernel_launch(void* const* d_in, const int* in_sizes, int n_in,
                              void* d_out, int out_size) {
    const float* X     = (const float*)d_in[0];   // [N_NODES, 128]
    const float* W     = (const float*)d_in[1];   // [128, 128]
    const float* bias  = (const float*)d_in[2];   // [128]
    const int*   v_idx = (const int*)d_in[3];     // [NNZ]
    const int*   e_idx = (const int*)d_in[4];     // [NNZ]
    float* out = (float*)d_out;                   // [N_NODES, 128]

    (void)in_sizes; (void)n_in; (void)out_size;

    cudaFuncSetAttribute(gemm_kernel, cudaFuncAttributeMaxDynamicSharedMemorySize,
                         GEMM_SMEM_BYTES);

    zero_counts_kernel<<<(N_NODES + 255) / 256, 256>>>();
    degree_kernel<<<(NNZ + 255) / 256, 256>>>(v_idx, e_idx);

    {
        // get symbol addresses via device-global references inside kernels; scans
        // take raw pointers, so resolve them host-side once per call (cheap, capture-safe).
        int *cnt_e_p, *cnt_v_p, *offs_e_p, *offs_v_p;
        cudaGetSymbolAddress((void**)&cnt_e_p, g_cnt_e);
        cudaGetSymbolAddress((void**)&cnt_v_p, g_cnt_v);
        cudaGetSymbolAddress((void**)&offs_e_p, g_offs_e);
        cudaGetSymbolAddress((void**)&offs_v_p, g_offs_v);
        scan_kernel<<<1, 1024>>>(cnt_e_p, N_EDGES, offs_e_p);
        scan_kernel<<<1, 1024>>>(cnt_v_p, N_NODES, offs_v_p);
    }

    init_kernel<<<(N_NODES + 255) / 256, 256>>>();
    fill_kernel<<<(NNZ + 255) / 256, 256>>>(v_idx, e_idx);

    gemm_kernel<<<(N_NODES + BM - 1) / BM, 256, GEMM_SMEM_BYTES>>>(X, W, bias);

    edge_reduce_kernel<<<(N_EDGES * 32 + 255) / 256, 256>>>();
    node_reduce_kernel<<<(N_NODES * 32 + 255) / 256, 256>>>(out);
}

// round 2
// speedup vs baseline: 1.2275x; 1.2275x over previous
#include <cuda_runtime.h>
#include <math.h>

#define N_NODES 100000
#define N_EDGES 20000
#define NNZ     1600000
#define D       128

// ---------------- scratch (device globals: allocation-free rule) ----------------
__device__ int   g_cnt_v[N_NODES];
__device__ int   g_cnt_e[N_EDGES];
__device__ int   g_offs_v[N_NODES + 1];
__device__ int   g_offs_e[N_EDGES + 1];
__device__ int   g_cur_v[N_NODES];
__device__ int   g_cur_e[N_EDGES];
__device__ int   g_part_v[128];     // block partial sums for node scan (98 used)
__device__ int   g_part_e[128];     // block partial sums for edge scan (20 used)
__device__ float g_inv_sqrt_dv[N_NODES];
__device__ float g_inv_de[N_EDGES];
__device__ int   g_edge_adj[NNZ];   // per-edge list of vertex ids
__device__ int   g_node_adj[NNZ];   // per-node list of edge ids
__device__ float g_Xs[(size_t)N_NODES * D];   // (X@W + b) * dv^-1/2
__device__ float g_Ye[(size_t)N_EDGES * D];   // edge aggregates * de^-1

// ---------------- 0: zero counters ----------------
__global__ void zero_counts_kernel() {
    int i = blockIdx.x * blockDim.x + threadIdx.x;
    if (i < N_NODES) g_cnt_v[i] = 0;
    if (i < N_EDGES) g_cnt_e[i] = 0;
}

// ---------------- 1: degree histograms ----------------
__global__ void degree_kernel(const int* __restrict__ v_idx, const int* __restrict__ e_idx) {
    int i = blockIdx.x * blockDim.x + threadIdx.x;
    if (i < NNZ) {
        atomicAdd(&g_cnt_v[v_idx[i]], 1);
        atomicAdd(&g_cnt_e[e_idx[i]], 1);
    }
}

// ---------------- 2a: per-block exclusive scan + block sums ----------------
__global__ void scanA_kernel(const int* __restrict__ in, int n,
                             int* __restrict__ out, int* __restrict__ partials) {
    __shared__ int wsum[32];
    int tid = threadIdx.x;                       // 1024
    int i = blockIdx.x * 1024 + tid;
    int x = (i < n) ? in[i] : 0;
    int v = x;
    #pragma unroll
    for (int o = 1; o < 32; o <<= 1) {
        int t = __shfl_up_sync(0xFFFFFFFFu, v, o);
        if ((tid & 31) >= o) v += t;
    }
    if ((tid & 31) == 31) wsum[tid >> 5] = v;
    __syncthreads();
    if (tid < 32) {
        int w = wsum[tid];
        #pragma unroll
        for (int o = 1; o < 32; o <<= 1) {
            int t = __shfl_up_sync(0xFFFFFFFFu, w, o);
            if (tid >= o) w += t;
        }
        wsum[tid] = w;
    }
    __syncthreads();
    int warppre = (tid >= 32) ? wsum[(tid >> 5) - 1] : 0;
    int incl = v + warppre;
    if (i < n) out[i] = incl - x;                // block-local exclusive
    if (tid == 1023) partials[blockIdx.x] = incl; // block total
}

// ---------------- 2b: scan block sums (single small block), write grand total ----------------
__global__ void scanB_kernel(int* __restrict__ partials, int nblocks,
                             int* __restrict__ total_out) {
    __shared__ int wsum[4];
    int tid = threadIdx.x;                       // 128 threads (nblocks <= 128)
    int x = (tid < nblocks) ? partials[tid] : 0;
    int v = x;
    #pragma unroll
    for (int o = 1; o < 32; o <<= 1) {
        int t = __shfl_up_sync(0xFFFFFFFFu, v, o);
        if ((tid & 31) >= o) v += t;
    }
    if ((tid & 31) == 31) wsum[tid >> 5] = v;
    __syncthreads();
    if (tid < 4) {
        int w = wsum[tid];
        #pragma unroll
        for (int o = 1; o < 4; o <<= 1) {
            int t = __shfl_up_sync(0xFu, w, o);
            if (tid >= o) w += t;
        }
        wsum[tid] = w;
    }
    __syncthreads();
    int warppre = (tid >= 32) ? wsum[(tid >> 5) - 1] : 0;
    int incl = v + warppre;
    if (tid < nblocks) partials[tid] = incl - x; // exclusive
    if (tid == nblocks - 1) *total_out = incl;   // grand total -> offs[n]
}

// ---------------- 2c: uniform add ----------------
__global__ void scanC_kernel(int* __restrict__ out, int n, const int* __restrict__ partials) {
    int i = blockIdx.x * 1024 + threadIdx.x;
    if (i < n) out[i] += partials[blockIdx.x];
}

// ---------------- 3: inverse degree factors + cursor init ----------------
__global__ void init_kernel() {
    int i = blockIdx.x * blockDim.x + threadIdx.x;
    if (i < N_NODES) {
        int c = g_cnt_v[i];
        g_inv_sqrt_dv[i] = (c > 0) ? rsqrtf((float)c) : 0.0f;
        g_cur_v[i] = g_offs_v[i];
    }
    if (i < N_EDGES) {
        int c = g_cnt_e[i];
        g_inv_de[i] = (c > 0) ? (1.0f / (float)c) : 0.0f;
        g_cur_e[i] = g_offs_e[i];
    }
}

// ---------------- 4: CSR fill (both directions) ----------------
__global__ void fill_kernel(const int* __restrict__ v_idx, const int* __restrict__ e_idx) {
    int i = blockIdx.x * blockDim.x + threadIdx.x;
    if (i < NNZ) {
        int v = v_idx[i];
        int e = e_idx[i];
        int pe = atomicAdd(&g_cur_e[e], 1);
        g_edge_adj[pe] = v;
        int pv = atomicAdd(&g_cur_v[v], 1);
        g_node_adj[pv] = e;
    }
}

// ---------------- 5: GEMM  Xs = (X @ W + b) * inv_sqrt_dv ----------------
#define BM 64
#define XS_STRIDE 132
#define GEMM_SMEM_BYTES ((128 * 128 + BM * XS_STRIDE + 128) * 4)

__global__ void __launch_bounds__(256, 2)
gemm_kernel(const float* __restrict__ X, const float* __restrict__ W,
            const float* __restrict__ bias) {
    extern __shared__ float sm[];
    float* Wsm = sm;                       // [128][128]
    float* Xsm = sm + 128 * 128;           // [BM][XS_STRIDE]
    float* bsm = Xsm + BM * XS_STRIDE;     // [128]

    int tid = threadIdx.x;                 // 256
    int row0 = blockIdx.x * BM;

    for (int i = tid; i < 128 * 32; i += 256)
        ((float4*)Wsm)[i] = ((const float4*)W)[i];
    if (tid < 32)
        ((float4*)bsm)[tid] = ((const float4*)bias)[tid];
    for (int i = tid; i < BM * 32; i += 256) {
        int m = i >> 5, kq = i & 31;
        int gr = row0 + m;
        float4 vv = (gr < N_NODES) ? ((const float4*)(X + (size_t)gr * D))[kq]
                                   : make_float4(0.f, 0.f, 0.f, 0.f);
        *((float4*)(Xsm + m * XS_STRIDE + kq * 4)) = vv;
    }
    __syncthreads();

    int tx = tid & 31;
    int ty = tid >> 5;
    int c0 = tx * 4, r0 = ty * 8;

    float acc[8][4];
    #pragma unroll
    for (int j = 0; j < 8; j++) {
        acc[j][0] = 0.f; acc[j][1] = 0.f; acc[j][2] = 0.f; acc[j][3] = 0.f;
    }

    #pragma unroll 8
    for (int k = 0; k < 128; k++) {
        float4 b4 = *(const float4*)(Wsm + k * 128 + c0);
        #pragma unroll
        for (int j = 0; j < 8; j++) {
            float a = Xsm[(r0 + j) * XS_STRIDE + k];
            acc[j][0] = fmaf(a, b4.x, acc[j][0]);
            acc[j][1] = fmaf(a, b4.y, acc[j][1]);
            acc[j][2] = fmaf(a, b4.z, acc[j][2]);
            acc[j][3] = fmaf(a, b4.w, acc[j][3]);
        }
    }

    float4 bb = *(const float4*)(bsm + c0);
    #pragma unroll
    for (int j = 0; j < 8; j++) {
        int gr = row0 + r0 + j;
        if (gr < N_NODES) {
            float s = g_inv_sqrt_dv[gr];
            float4 o;
            o.x = (acc[j][0] + bb.x) * s;
            o.y = (acc[j][1] + bb.y) * s;
            o.z = (acc[j][2] + bb.z) * s;
            o.w = (acc[j][3] + bb.w) * s;
            ((float4*)(g_Xs + (size_t)gr * D))[tx] = o;
        }
    }
}

// ---------------- 6: edge gather-reduce ----------------
__global__ void edge_reduce_kernel() {
    int gw = (blockIdx.x * blockDim.x + threadIdx.x) >> 5;
    if (gw >= N_EDGES) return;
    int lane = threadIdx.x & 31;
    int beg = g_offs_e[gw], end = g_offs_e[gw + 1];
    const float4* Xs4 = (const float4*)g_Xs;
    float sx = 0.f, sy = 0.f, sz = 0.f, sw = 0.f;
    int j = beg;
    for (; j + 4 <= end; j += 4) {
        int v0 = g_edge_adj[j + 0];
        int v1 = g_edge_adj[j + 1];
        int v2 = g_edge_adj[j + 2];
        int v3 = g_edge_adj[j + 3];
        float4 p0 = Xs4[(size_t)v0 * 32 + lane];
        float4 p1 = Xs4[(size_t)v1 * 32 + lane];
        float4 p2 = Xs4[(size_t)v2 * 32 + lane];
        float4 p3 = Xs4[(size_t)v3 * 32 + lane];
        sx += p0.x + p1.x + p2.x + p3.x;
        sy += p0.y + p1.y + p2.y + p3.y;
        sz += p0.z + p1.z + p2.z + p3.z;
        sw += p0.w + p1.w + p2.w + p3.w;
    }
    for (; j < end; j++) {
        int v = g_edge_adj[j];
        float4 p = Xs4[(size_t)v * 32 + lane];
        sx += p.x; sy += p.y; sz += p.z; sw += p.w;
    }
    float s = g_inv_de[gw];
    ((float4*)g_Ye)[(size_t)gw * 32 + lane] = make_float4(sx * s, sy * s, sz * s, sw * s);
}

// ---------------- 7: node gather-reduce + relu ----------------
__global__ void node_reduce_kernel(float* __restrict__ out) {
    int gw = (blockIdx.x * blockDim.x + threadIdx.x) >> 5;
    if (gw >= N_NODES) return;
    int lane = threadIdx.x & 31;
    int beg = g_offs_v[gw], end = g_offs_v[gw + 1];
    const float4* Ye4 = (const float4*)g_Ye;
    float sx = 0.f, sy = 0.f, sz = 0.f, sw = 0.f;
    int j = beg;
    for (; j + 4 <= end; j += 4) {
        int e0 = g_node_adj[j + 0];
        int e1 = g_node_adj[j + 1];
        int e2 = g_node_adj[j + 2];
        int e3 = g_node_adj[j + 3];
        float4 p0 = Ye4[(size_t)e0 * 32 + lane];
        float4 p1 = Ye4[(size_t)e1 * 32 + lane];
        float4 p2 = Ye4[(size_t)e2 * 32 + lane];
        float4 p3 = Ye4[(size_t)e3 * 32 + lane];
        sx += p0.x + p1.x + p2.x + p3.x;
        sy += p0.y + p1.y + p2.y + p3.y;
        sz += p0.z + p1.z + p2.z + p3.z;
        sw += p0.w + p1.w + p2.w + p3.w;
    }
    for (; j < end; j++) {
        int e = g_node_adj[j];
        float4 p = Ye4[(size_t)e * 32 + lane];
        sx += p.x; sy += p.y; sz += p.z; sw += p.w;
    }
    float s = g_inv_sqrt_dv[gw];
    float4 o;
    o.x = fmaxf(sx * s, 0.f);
    o.y = fmaxf(sy * s, 0.f);
    o.z = fmaxf(sz * s, 0.f);
    o.w = fmaxf(sw * s, 0.f);
    ((float4*)out)[(size_t)gw * 32 + lane] = o;
}

// ---------------- launch ----------------
extern "C" void kernel_launch(void* const* d_in, const int* in_sizes, int n_in,
                              void* d_out, int out_size) {
    const float* X     = (const float*)d_in[0];
    const float* W     = (const float*)d_in[1];
    const float* bias  = (const float*)d_in[2];
    const int*   v_idx = (const int*)d_in[3];
    const int*   e_idx = (const int*)d_in[4];
    float* out = (float*)d_out;

    (void)in_sizes; (void)n_in; (void)out_size;

    cudaFuncSetAttribute(gemm_kernel, cudaFuncAttributeMaxDynamicSharedMemorySize,
                         GEMM_SMEM_BYTES);

    int *cnt_e_p, *cnt_v_p, *offs_e_p, *offs_v_p, *part_v_p, *part_e_p;
    cudaGetSymbolAddress((void**)&cnt_e_p, g_cnt_e);
    cudaGetSymbolAddress((void**)&cnt_v_p, g_cnt_v);
    cudaGetSymbolAddress((void**)&offs_e_p, g_offs_e);
    cudaGetSymbolAddress((void**)&offs_v_p, g_offs_v);
    cudaGetSymbolAddress((void**)&part_v_p, g_part_v);
    cudaGetSymbolAddress((void**)&part_e_p, g_part_e);

    zero_counts_kernel<<<(N_NODES + 255) / 256, 256>>>();
    degree_kernel<<<(NNZ + 255) / 256, 256>>>(v_idx, e_idx);

    const int NB_V = (N_NODES + 1023) / 1024;   // 98
    const int NB_E = (N_EDGES + 1023) / 1024;   // 20
    scanA_kernel<<<NB_V, 1024>>>(cnt_v_p, N_NODES, offs_v_p, part_v_p);
    scanA_kernel<<<NB_E, 1024>>>(cnt_e_p, N_EDGES, offs_e_p, part_e_p);
    scanB_kernel<<<1, 128>>>(part_v_p, NB_V, offs_v_p + N_NODES);
    scanB_kernel<<<1, 128>>>(part_e_p, NB_E, offs_e_p + N_EDGES);
    scanC_kernel<<<NB_V, 1024>>>(offs_v_p, N_NODES, part_v_p);
    scanC_kernel<<<NB_E, 1024>>>(offs_e_p, N_EDGES, part_e_p);

    init_kernel<<<(N_NODES + 255) / 256, 256>>>();
    fill_kernel<<<(NNZ + 255) / 256, 256>>>(v_idx, e_idx);

    gemm_kernel<<<(N_NODES + BM - 1) / BM, 256, GEMM_SMEM_BYTES>>>(X, W, bias);

    edge_reduce_kernel<<<(N_EDGES * 32 + 255) / 256, 256>>>();
    node_reduce_kernel<<<(N_NODES * 32 + 255) / 256, 256>>>(out);
}

// round 3
// speedup vs baseline: 1.6359x; 1.3328x over previous
#include <cuda_runtime.h>
#include <math.h>

#define N_NODES 100000
#define N_EDGES 20000
#define NNZ     1600000
#define D       128

// ---------------- scratch (device globals: allocation-free rule) ----------------
__device__ int   g_cnt_v[N_NODES];
__device__ int   g_cnt_e[N_EDGES];
__device__ int   g_offs_v[N_NODES + 1];
__device__ int   g_offs_e[N_EDGES + 1];
__device__ int   g_cur_v[N_NODES];
__device__ int   g_cur_e[N_EDGES];
__device__ int   g_part_v[128];
__device__ int   g_part_e[128];
__device__ float g_inv_sqrt_dv[N_NODES];
__device__ float g_inv_de[N_EDGES];
__device__ int   g_edge_adj[NNZ];                 // per-edge list of vertex ids
__device__ int   g_node_adj[NNZ];                 // per-node list of edge ids
__device__ float g_Yp[(size_t)N_EDGES * D];       // inv_de * H^T Dv^-1/2 X
__device__ float g_se[N_EDGES];                   // inv_de * H^T Dv^-1/2 1
__device__ float g_Ye[(size_t)N_EDGES * D];       // Yp @ W + se*b

// ---------------- 0: zero counters ----------------
__global__ void zero_counts_kernel() {
    int i = blockIdx.x * blockDim.x + threadIdx.x;
    if (i < N_NODES) g_cnt_v[i] = 0;
    if (i < N_EDGES) g_cnt_e[i] = 0;
}

// ---------------- 1: degree histograms ----------------
__global__ void degree_kernel(const int* __restrict__ v_idx, const int* __restrict__ e_idx) {
    int i = blockIdx.x * blockDim.x + threadIdx.x;
    if (i < NNZ) {
        atomicAdd(&g_cnt_v[v_idx[i]], 1);
        atomicAdd(&g_cnt_e[e_idx[i]], 1);
    }
}

// ---------------- 2a: per-block exclusive scan + block sums ----------------
__global__ void scanA_kernel(const int* __restrict__ in, int n,
                             int* __restrict__ out, int* __restrict__ partials) {
    __shared__ int wsum[32];
    int tid = threadIdx.x;                       // 1024
    int i = blockIdx.x * 1024 + tid;
    int x = (i < n) ? in[i] : 0;
    int v = x;
    #pragma unroll
    for (int o = 1; o < 32; o <<= 1) {
        int t = __shfl_up_sync(0xFFFFFFFFu, v, o);
        if ((tid & 31) >= o) v += t;
    }
    if ((tid & 31) == 31) wsum[tid >> 5] = v;
    __syncthreads();
    if (tid < 32) {
        int w = wsum[tid];
        #pragma unroll
        for (int o = 1; o < 32; o <<= 1) {
            int t = __shfl_up_sync(0xFFFFFFFFu, w, o);
            if (tid >= o) w += t;
        }
        wsum[tid] = w;
    }
    __syncthreads();
    int warppre = (tid >= 32) ? wsum[(tid >> 5) - 1] : 0;
    int incl = v + warppre;
    if (i < n) out[i] = incl - x;
    if (tid == 1023) partials[blockIdx.x] = incl;
}

// ---------------- 2b: scan block sums, write grand total ----------------
__global__ void scanB_kernel(int* __restrict__ partials, int nblocks,
                             int* __restrict__ total_out) {
    __shared__ int wsum[4];
    int tid = threadIdx.x;                       // 128
    int x = (tid < nblocks) ? partials[tid] : 0;
    int v = x;
    #pragma unroll
    for (int o = 1; o < 32; o <<= 1) {
        int t = __shfl_up_sync(0xFFFFFFFFu, v, o);
        if ((tid & 31) >= o) v += t;
    }
    if ((tid & 31) == 31) wsum[tid >> 5] = v;
    __syncthreads();
    if (tid < 4) {
        int w = wsum[tid];
        #pragma unroll
        for (int o = 1; o < 4; o <<= 1) {
            int t = __shfl_up_sync(0xFu, w, o);
            if (tid >= o) w += t;
        }
        wsum[tid] = w;
    }
    __syncthreads();
    int warppre = (tid >= 32) ? wsum[(tid >> 5) - 1] : 0;
    int incl = v + warppre;
    if (tid < nblocks) partials[tid] = incl - x;
    if (tid == nblocks - 1) *total_out = incl;
}

// ---------------- 2c: uniform add ----------------
__global__ void scanC_kernel(int* __restrict__ out, int n, const int* __restrict__ partials) {
    int i = blockIdx.x * 1024 + threadIdx.x;
    if (i < n) out[i] += partials[blockIdx.x];
}

// ---------------- 3: inverse degree factors + cursor init ----------------
__global__ void init_kernel() {
    int i = blockIdx.x * blockDim.x + threadIdx.x;
    if (i < N_NODES) {
        int c = g_cnt_v[i];
        g_inv_sqrt_dv[i] = (c > 0) ? rsqrtf((float)c) : 0.0f;
        g_cur_v[i] = g_offs_v[i];
    }
    if (i < N_EDGES) {
        int c = g_cnt_e[i];
        g_inv_de[i] = (c > 0) ? (1.0f / (float)c) : 0.0f;
        g_cur_e[i] = g_offs_e[i];
    }
}

// ---------------- 4: CSR fill (both directions) ----------------
__global__ void fill_kernel(const int* __restrict__ v_idx, const int* __restrict__ e_idx) {
    int i = blockIdx.x * blockDim.x + threadIdx.x;
    if (i < NNZ) {
        int v = v_idx[i];
        int e = e_idx[i];
        int pe = atomicAdd(&g_cur_e[e], 1);
        g_edge_adj[pe] = v;
        int pv = atomicAdd(&g_cur_v[v], 1);
        g_node_adj[pv] = e;
    }
}

// ---------------- 5: edge gather-reduce on RAW X:
//   Yp[e] = inv_de[e] * sum_{v in e} inv_sqrt_dv[v] * X[v]
//   se[e] = inv_de[e] * sum_{v in e} inv_sqrt_dv[v]
__global__ void edge_reduce_kernel(const float* __restrict__ X) {
    int gw = (blockIdx.x * blockDim.x + threadIdx.x) >> 5;
    if (gw >= N_EDGES) return;
    int lane = threadIdx.x & 31;
    int beg = g_offs_e[gw], end = g_offs_e[gw + 1];
    const float4* X4 = (const float4*)X;
    float sx = 0.f, sy = 0.f, sz = 0.f, sw = 0.f, ssum = 0.f;
    int j = beg;
    for (; j + 4 <= end; j += 4) {
        int v0 = g_edge_adj[j + 0];
        int v1 = g_edge_adj[j + 1];
        int v2 = g_edge_adj[j + 2];
        int v3 = g_edge_adj[j + 3];
        float s0 = g_inv_sqrt_dv[v0];
        float s1 = g_inv_sqrt_dv[v1];
        float s2 = g_inv_sqrt_dv[v2];
        float s3 = g_inv_sqrt_dv[v3];
        float4 p0 = X4[(size_t)v0 * 32 + lane];
        float4 p1 = X4[(size_t)v1 * 32 + lane];
        float4 p2 = X4[(size_t)v2 * 32 + lane];
        float4 p3 = X4[(size_t)v3 * 32 + lane];
        sx = fmaf(s0, p0.x, fmaf(s1, p1.x, fmaf(s2, p2.x, fmaf(s3, p3.x, sx))));
        sy = fmaf(s0, p0.y, fmaf(s1, p1.y, fmaf(s2, p2.y, fmaf(s3, p3.y, sy))));
        sz = fmaf(s0, p0.z, fmaf(s1, p1.z, fmaf(s2, p2.z, fmaf(s3, p3.z, sz))));
        sw = fmaf(s0, p0.w, fmaf(s1, p1.w, fmaf(s2, p2.w, fmaf(s3, p3.w, sw))));
        ssum += s0 + s1 + s2 + s3;
    }
    for (; j < end; j++) {
        int v = g_edge_adj[j];
        float s = g_inv_sqrt_dv[v];
        float4 p = X4[(size_t)v * 32 + lane];
        sx = fmaf(s, p.x, sx);
        sy = fmaf(s, p.y, sy);
        sz = fmaf(s, p.z, sz);
        sw = fmaf(s, p.w, sw);
        ssum += s;
    }
    float s = g_inv_de[gw];
    ((float4*)g_Yp)[(size_t)gw * 32 + lane] = make_float4(sx * s, sy * s, sz * s, sw * s);
    if (lane == 0) g_se[gw] = ssum * s;
}

// ---------------- 6: small GEMM  Ye = Yp @ W + se * b  (20000 rows) ----------------
#define BM 64
#define XS_STRIDE 132
#define GEMM_SMEM_BYTES ((128 * 128 + BM * XS_STRIDE + 128) * 4)

__global__ void __launch_bounds__(256)
gemm_edges_kernel(const float* __restrict__ W, const float* __restrict__ bias) {
    extern __shared__ float sm[];
    float* Wsm = sm;                       // [128][128]
    float* Ysm = sm + 128 * 128;           // [BM][XS_STRIDE]
    float* bsm = Ysm + BM * XS_STRIDE;     // [128]

    int tid = threadIdx.x;                 // 256
    int row0 = blockIdx.x * BM;

    for (int i = tid; i < 128 * 32; i += 256)
        ((float4*)Wsm)[i] = ((const float4*)W)[i];
    if (tid < 32)
        ((float4*)bsm)[tid] = ((const float4*)bias)[tid];
    for (int i = tid; i < BM * 32; i += 256) {
        int m = i >> 5, kq = i & 31;
        int gr = row0 + m;
        float4 vv = (gr < N_EDGES) ? ((const float4*)(g_Yp + (size_t)gr * D))[kq]
                                   : make_float4(0.f, 0.f, 0.f, 0.f);
        *((float4*)(Ysm + m * XS_STRIDE + kq * 4)) = vv;
    }
    __syncthreads();

    int tx = tid & 31;
    int ty = tid >> 5;
    int c0 = tx * 4, r0 = ty * 8;

    float acc[8][4];
    #pragma unroll
    for (int j = 0; j < 8; j++) {
        acc[j][0] = 0.f; acc[j][1] = 0.f; acc[j][2] = 0.f; acc[j][3] = 0.f;
    }

    #pragma unroll 8
    for (int k = 0; k < 128; k++) {
        float4 b4 = *(const float4*)(Wsm + k * 128 + c0);
        #pragma unroll
        for (int j = 0; j < 8; j++) {
            float a = Ysm[(r0 + j) * XS_STRIDE + k];
            acc[j][0] = fmaf(a, b4.x, acc[j][0]);
            acc[j][1] = fmaf(a, b4.y, acc[j][1]);
            acc[j][2] = fmaf(a, b4.z, acc[j][2]);
            acc[j][3] = fmaf(a, b4.w, acc[j][3]);
        }
    }

    float4 bb = *(const float4*)(bsm + c0);
    #pragma unroll
    for (int j = 0; j < 8; j++) {
        int gr = row0 + r0 + j;
        if (gr < N_EDGES) {
            float se = g_se[gr];
            float4 o;
            o.x = fmaf(se, bb.x, acc[j][0]);
            o.y = fmaf(se, bb.y, acc[j][1]);
            o.z = fmaf(se, bb.z, acc[j][2]);
            o.w = fmaf(se, bb.w, acc[j][3]);
            ((float4*)(g_Ye + (size_t)gr * D))[tx] = o;
        }
    }
}

// ---------------- 7: node gather-reduce + relu ----------------
__global__ void node_reduce_kernel(float* __restrict__ out) {
    int gw = (blockIdx.x * blockDim.x + threadIdx.x) >> 5;
    if (gw >= N_NODES) return;
    int lane = threadIdx.x & 31;
    int beg = g_offs_v[gw], end = g_offs_v[gw + 1];
    const float4* Ye4 = (const float4*)g_Ye;
    float sx = 0.f, sy = 0.f, sz = 0.f, sw = 0.f;
    int j = beg;
    for (; j + 4 <= end; j += 4) {
        int e0 = g_node_adj[j + 0];
        int e1 = g_node_adj[j + 1];
        int e2 = g_node_adj[j + 2];
        int e3 = g_node_adj[j + 3];
        float4 p0 = Ye4[(size_t)e0 * 32 + lane];
        float4 p1 = Ye4[(size_t)e1 * 32 + lane];
        float4 p2 = Ye4[(size_t)e2 * 32 + lane];
        float4 p3 = Ye4[(size_t)e3 * 32 + lane];
        sx += p0.x + p1.x + p2.x + p3.x;
        sy += p0.y + p1.y + p2.y + p3.y;
        sz += p0.z + p1.z + p2.z + p3.z;
        sw += p0.w + p1.w + p2.w + p3.w;
    }
    for (; j < end; j++) {
        int e = g_node_adj[j];
        float4 p = Ye4[(size_t)e * 32 + lane];
        sx += p.x; sy += p.y; sz += p.z; sw += p.w;
    }
    float s = g_inv_sqrt_dv[gw];
    float4 o;
    o.x = fmaxf(sx * s, 0.f);
    o.y = fmaxf(sy * s, 0.f);
    o.z = fmaxf(sz * s, 0.f);
    o.w = fmaxf(sw * s, 0.f);
    ((float4*)out)[(size_t)gw * 32 + lane] = o;
}

// ---------------- launch ----------------
extern "C" void kernel_launch(void* const* d_in, const int* in_sizes, int n_in,
                              void* d_out, int out_size) {
    const float* X     = (const float*)d_in[0];
    const float* W     = (const float*)d_in[1];
    const float* bias  = (const float*)d_in[2];
    const int*   v_idx = (const int*)d_in[3];
    const int*   e_idx = (const int*)d_in[4];
    float* out = (float*)d_out;

    (void)in_sizes; (void)n_in; (void)out_size;

    cudaFuncSetAttribute(gemm_edges_kernel, cudaFuncAttributeMaxDynamicSharedMemorySize,
                         GEMM_SMEM_BYTES);

    int *cnt_e_p, *cnt_v_p, *offs_e_p, *offs_v_p, *part_v_p, *part_e_p;
    cudaGetSymbolAddress((void**)&cnt_e_p, g_cnt_e);
    cudaGetSymbolAddress((void**)&cnt_v_p, g_cnt_v);
    cudaGetSymbolAddress((void**)&offs_e_p, g_offs_e);
    cudaGetSymbolAddress((void**)&offs_v_p, g_offs_v);
    cudaGetSymbolAddress((void**)&part_v_p, g_part_v);
    cudaGetSymbolAddress((void**)&part_e_p, g_part_e);

    zero_counts_kernel<<<(N_NODES + 255) / 256, 256>>>();
    degree_kernel<<<(NNZ + 255) / 256, 256>>>(v_idx, e_idx);

    const int NB_V = (N_NODES + 1023) / 1024;   // 98
    const int NB_E = (N_EDGES + 1023) / 1024;   // 20
    scanA_kernel<<<NB_V, 1024>>>(cnt_v_p, N_NODES, offs_v_p, part_v_p);
    scanA_kernel<<<NB_E, 1024>>>(cnt_e_p, N_EDGES, offs_e_p, part_e_p);
    scanB_kernel<<<1, 128>>>(part_v_p, NB_V, offs_v_p + N_NODES);
    scanB_kernel<<<1, 128>>>(part_e_p, NB_E, offs_e_p + N_EDGES);
    scanC_kernel<<<NB_V, 1024>>>(offs_v_p, N_NODES, part_v_p);
    scanC_kernel<<<NB_E, 1024>>>(offs_e_p, N_EDGES, part_e_p);

    init_kernel<<<(N_NODES + 255) / 256, 256>>>();
    fill_kernel<<<(NNZ + 255) / 256, 256>>>(v_idx, e_idx);

    edge_reduce_kernel<<<(N_EDGES * 32 + 255) / 256, 256>>>(X);
    gemm_edges_kernel<<<(N_EDGES + BM - 1) / BM, 256, GEMM_SMEM_BYTES>>>(W, bias);
    node_reduce_kernel<<<(N_NODES * 32 + 255) / 256, 256>>>(out);
}

// round 4
// speedup vs baseline: 1.7152x; 1.0484x over previous
#include <cuda_runtime.h>
#include <cuda_fp16.h>
#include <math.h>

#define N_NODES 100000
#define N_EDGES 20000
#define NNZ     1600000
#define D       128

// ---------------- scratch (device globals: allocation-free rule) ----------------
__device__ int   g_cnt_v[N_NODES];
__device__ int   g_cnt_e[N_EDGES];
__device__ int   g_offs_v[N_NODES + 1];
__device__ int   g_offs_e[N_EDGES + 1];
__device__ int   g_pos_v[NNZ];                    // per-entry rank within its node
__device__ int   g_pos_e[NNZ];                    // per-entry rank within its edge
__device__ int   g_part_v[128];
__device__ int   g_part_e[128];
__device__ float g_inv_sqrt_dv[N_NODES];
__device__ float g_inv_de[N_EDGES];
__device__ int   g_edge_adj[NNZ];                 // per-edge list of vertex ids
__device__ int   g_node_adj[NNZ];                 // per-node list of edge ids
__device__ unsigned g_Xh[(size_t)N_NODES * 64];   // X in half2 (bit patterns), 64 half2/row
__device__ float g_Yp[(size_t)N_EDGES * D];       // inv_de * H^T Dv^-1/2 X   (fp32)
__device__ float g_se[N_EDGES];                   // inv_de * H^T Dv^-1/2 1
__device__ unsigned g_Yeh[(size_t)N_EDGES * 64];  // Ye in half2, 64 half2/row

// ---------------- 0: zero counters ----------------
__global__ void zero_counts_kernel() {
    int i = blockIdx.x * blockDim.x + threadIdx.x;
    if (i < N_NODES) g_cnt_v[i] = 0;
    if (i < N_EDGES) g_cnt_e[i] = 0;
}

// ---------------- 0b: X -> half2 staging ----------------
__global__ void convert_X_kernel(const float* __restrict__ X) {
    int i = blockIdx.x * blockDim.x + threadIdx.x;   // over N_NODES*32 float4
    if (i < N_NODES * 32) {
        float4 p = ((const float4*)X)[i];
        __half2 a = __floats2half2_rn(p.x, p.y);
        __half2 b = __floats2half2_rn(p.z, p.w);
        uint2 r;
        r.x = *reinterpret_cast<const unsigned*>(&a);
        r.y = *reinterpret_cast<const unsigned*>(&b);
        ((uint2*)g_Xh)[i] = r;
    }
}

// ---------------- 1: degree histograms + per-entry rank capture ----------------
__global__ void degree_kernel(const int* __restrict__ v_idx, const int* __restrict__ e_idx) {
    int i = blockIdx.x * blockDim.x + threadIdx.x;
    if (i < NNZ) {
        g_pos_v[i] = atomicAdd(&g_cnt_v[v_idx[i]], 1);
        g_pos_e[i] = atomicAdd(&g_cnt_e[e_idx[i]], 1);
    }
}

// ---------------- 2a: per-block exclusive scan + block sums ----------------
__global__ void scanA_kernel(const int* __restrict__ in, int n,
                             int* __restrict__ out, int* __restrict__ partials) {
    __shared__ int wsum[32];
    int tid = threadIdx.x;                       // 1024
    int i = blockIdx.x * 1024 + tid;
    int x = (i < n) ? in[i] : 0;
    int v = x;
    #pragma unroll
    for (int o = 1; o < 32; o <<= 1) {
        int t = __shfl_up_sync(0xFFFFFFFFu, v, o);
        if ((tid & 31) >= o) v += t;
    }
    if ((tid & 31) == 31) wsum[tid >> 5] = v;
    __syncthreads();
    if (tid < 32) {
        int w = wsum[tid];
        #pragma unroll
        for (int o = 1; o < 32; o <<= 1) {
            int t = __shfl_up_sync(0xFFFFFFFFu, w, o);
            if (tid >= o) w += t;
        }
        wsum[tid] = w;
    }
    __syncthreads();
    int warppre = (tid >= 32) ? wsum[(tid >> 5) - 1] : 0;
    int incl = v + warppre;
    if (i < n) out[i] = incl - x;
    if (tid == 1023) partials[blockIdx.x] = incl;
}

// ---------------- 2b: scan block sums, write grand total ----------------
__global__ void scanB_kernel(int* __restrict__ partials, int nblocks,
                             int* __restrict__ total_out) {
    __shared__ int wsum[4];
    int tid = threadIdx.x;                       // 128
    int x = (tid < nblocks) ? partials[tid] : 0;
    int v = x;
    #pragma unroll
    for (int o = 1; o < 32; o <<= 1) {
        int t = __shfl_up_sync(0xFFFFFFFFu, v, o);
        if ((tid & 31) >= o) v += t;
    }
    if ((tid & 31) == 31) wsum[tid >> 5] = v;
    __syncthreads();
    if (tid < 4) {
        int w = wsum[tid];
        #pragma unroll
        for (int o = 1; o < 4; o <<= 1) {
            int t = __shfl_up_sync(0xFu, w, o);
            if (tid >= o) w += t;
        }
        wsum[tid] = w;
    }
    __syncthreads();
    int warppre = (tid >= 32) ? wsum[(tid >> 5) - 1] : 0;
    int incl = v + warppre;
    if (tid < nblocks) partials[tid] = incl - x;
    if (tid == nblocks - 1) *total_out = incl;
}

// ---------------- 2c: uniform add ----------------
__global__ void scanC_kernel(int* __restrict__ out, int n, const int* __restrict__ partials) {
    int i = blockIdx.x * 1024 + threadIdx.x;
    if (i < n) out[i] += partials[blockIdx.x];
}

// ---------------- 3: inverse degree factors ----------------
__global__ void init_kernel() {
    int i = blockIdx.x * blockDim.x + threadIdx.x;
    if (i < N_NODES) {
        int c = g_cnt_v[i];
        g_inv_sqrt_dv[i] = (c > 0) ? rsqrtf((float)c) : 0.0f;
    }
    if (i < N_EDGES) {
        int c = g_cnt_e[i];
        g_inv_de[i] = (c > 0) ? (1.0f / (float)c) : 0.0f;
    }
}

// ---------------- 4: CSR fill (atomic-free: offsets + captured ranks) ----------------
__global__ void fill_kernel(const int* __restrict__ v_idx, const int* __restrict__ e_idx) {
    int i = blockIdx.x * blockDim.x + threadIdx.x;
    if (i < NNZ) {
        int v = v_idx[i];
        int e = e_idx[i];
        g_edge_adj[g_offs_e[e] + g_pos_e[i]] = v;
        g_node_adj[g_offs_v[v] + g_pos_v[i]] = e;
    }
}

// ---------------- 5: edge gather-reduce on half2-staged X:
//   Yp[e] = inv_de[e] * sum_{v in e} inv_sqrt_dv[v] * X[v];  se[e] likewise for 1
__global__ void edge_reduce_kernel() {
    int gw = (blockIdx.x * blockDim.x + threadIdx.x) >> 5;
    if (gw >= N_EDGES) return;
    int lane = threadIdx.x & 31;
    int beg = g_offs_e[gw], end = g_offs_e[gw + 1];
    const uint2* Xh2 = (const uint2*)g_Xh;       // 32 uint2 per row
    float sx = 0.f, sy = 0.f, sz = 0.f, sw = 0.f, ssum = 0.f;
    int j = beg;
    for (; j + 4 <= end; j += 4) {
        int v0 = g_edge_adj[j + 0];
        int v1 = g_edge_adj[j + 1];
        int v2 = g_edge_adj[j + 2];
        int v3 = g_edge_adj[j + 3];
        float s0 = g_inv_sqrt_dv[v0];
        float s1 = g_inv_sqrt_dv[v1];
        float s2 = g_inv_sqrt_dv[v2];
        float s3 = g_inv_sqrt_dv[v3];
        uint2 q0 = Xh2[(size_t)v0 * 32 + lane];
        uint2 q1 = Xh2[(size_t)v1 * 32 + lane];
        uint2 q2 = Xh2[(size_t)v2 * 32 + lane];
        uint2 q3 = Xh2[(size_t)v3 * 32 + lane];
        float2 a0 = __half22float2(*reinterpret_cast<__half2*>(&q0.x));
        float2 b0 = __half22float2(*reinterpret_cast<__half2*>(&q0.y));
        float2 a1 = __half22float2(*reinterpret_cast<__half2*>(&q1.x));
        float2 b1 = __half22float2(*reinterpret_cast<__half2*>(&q1.y));
        float2 a2 = __half22float2(*reinterpret_cast<__half2*>(&q2.x));
        float2 b2 = __half22float2(*reinterpret_cast<__half2*>(&q2.y));
        float2 a3 = __half22float2(*reinterpret_cast<__half2*>(&q3.x));
        float2 b3 = __half22float2(*reinterpret_cast<__half2*>(&q3.y));
        sx = fmaf(s0, a0.x, fmaf(s1, a1.x, fmaf(s2, a2.x, fmaf(s3, a3.x, sx))));
        sy = fmaf(s0, a0.y, fmaf(s1, a1.y, fmaf(s2, a2.y, fmaf(s3, a3.y, sy))));
        sz = fmaf(s0, b0.x, fmaf(s1, b1.x, fmaf(s2, b2.x, fmaf(s3, b3.x, sz))));
        sw = fmaf(s0, b0.y, fmaf(s1, b1.y, fmaf(s2, b2.y, fmaf(s3, b3.y, sw))));
        ssum += s0 + s1 + s2 + s3;
    }
    for (; j < end; j++) {
        int v = g_edge_adj[j];
        float s = g_inv_sqrt_dv[v];
        uint2 q = Xh2[(size_t)v * 32 + lane];
        float2 a = __half22float2(*reinterpret_cast<__half2*>(&q.x));
        float2 b = __half22float2(*reinterpret_cast<__half2*>(&q.y));
        sx = fmaf(s, a.x, sx);
        sy = fmaf(s, a.y, sy);
        sz = fmaf(s, b.x, sz);
        sw = fmaf(s, b.y, sw);
        ssum += s;
    }
    float s = g_inv_de[gw];
    ((float4*)g_Yp)[(size_t)gw * 32 + lane] = make_float4(sx * s, sy * s, sz * s, sw * s);
    if (lane == 0) g_se[gw] = ssum * s;
}

// ---------------- 6: small GEMM  Ye = Yp @ W + se * b  (fp32 math, half2 output) ----------------
#define BM 64
#define XS_STRIDE 132
#define GEMM_SMEM_BYTES ((128 * 128 + BM * XS_STRIDE + 128) * 4)

__global__ void __launch_bounds__(256)
gemm_edges_kernel(const float* __restrict__ W, const float* __restrict__ bias) {
    extern __shared__ float sm[];
    float* Wsm = sm;                       // [128][128]
    float* Ysm = sm + 128 * 128;           // [BM][XS_STRIDE]
    float* bsm = Ysm + BM * XS_STRIDE;     // [128]

    int tid = threadIdx.x;                 // 256
    int row0 = blockIdx.x * BM;

    for (int i = tid; i < 128 * 32; i += 256)
        ((float4*)Wsm)[i] = ((const float4*)W)[i];
    if (tid < 32)
        ((float4*)bsm)[tid] = ((const float4*)bias)[tid];
    for (int i = tid; i < BM * 32; i += 256) {
        int m = i >> 5, kq = i & 31;
        int gr = row0 + m;
        float4 vv = (gr < N_EDGES) ? ((const float4*)(g_Yp + (size_t)gr * D))[kq]
                                   : make_float4(0.f, 0.f, 0.f, 0.f);
        *((float4*)(Ysm + m * XS_STRIDE + kq * 4)) = vv;
    }
    __syncthreads();

    int tx = tid & 31;
    int ty = tid >> 5;
    int c0 = tx * 4, r0 = ty * 8;

    float acc[8][4];
    #pragma unroll
    for (int j = 0; j < 8; j++) {
        acc[j][0] = 0.f; acc[j][1] = 0.f; acc[j][2] = 0.f; acc[j][3] = 0.f;
    }

    #pragma unroll 8
    for (int k = 0; k < 128; k++) {
        float4 b4 = *(const float4*)(Wsm + k * 128 + c0);
        #pragma unroll
        for (int j = 0; j < 8; j++) {
            float a = Ysm[(r0 + j) * XS_STRIDE + k];
            acc[j][0] = fmaf(a, b4.x, acc[j][0]);
            acc[j][1] = fmaf(a, b4.y, acc[j][1]);
            acc[j][2] = fmaf(a, b4.z, acc[j][2]);
            acc[j][3] = fmaf(a, b4.w, acc[j][3]);
        }
    }

    float4 bb = *(const float4*)(bsm + c0);
    #pragma unroll
    for (int j = 0; j < 8; j++) {
        int gr = row0 + r0 + j;
        if (gr < N_EDGES) {
            float se = g_se[gr];
            float ox = fmaf(se, bb.x, acc[j][0]);
            float oy = fmaf(se, bb.y, acc[j][1]);
            float oz = fmaf(se, bb.z, acc[j][2]);
            float ow = fmaf(se, bb.w, acc[j][3]);
            __half2 h0 = __floats2half2_rn(ox, oy);
            __half2 h1 = __floats2half2_rn(oz, ow);
            uint2 r;
            r.x = *reinterpret_cast<const unsigned*>(&h0);
            r.y = *reinterpret_cast<const unsigned*>(&h1);
            ((uint2*)g_Yeh)[(size_t)gr * 32 + tx] = r;
        }
    }
}

// ---------------- 7: node gather-reduce (half2 Ye) + relu ----------------
__global__ void node_reduce_kernel(float* __restrict__ out) {
    int gw = (blockIdx.x * blockDim.x + threadIdx.x) >> 5;
    if (gw >= N_NODES) return;
    int lane = threadIdx.x & 31;
    int beg = g_offs_v[gw], end = g_offs_v[gw + 1];
    const uint2* Ye2 = (const uint2*)g_Yeh;
    float sx = 0.f, sy = 0.f, sz = 0.f, sw = 0.f;
    int j = beg;
    for (; j + 4 <= end; j += 4) {
        int e0 = g_node_adj[j + 0];
        int e1 = g_node_adj[j + 1];
        int e2 = g_node_adj[j + 2];
        int e3 = g_node_adj[j + 3];
        uint2 q0 = Ye2[(size_t)e0 * 32 + lane];
        uint2 q1 = Ye2[(size_t)e1 * 32 + lane];
        uint2 q2 = Ye2[(size_t)e2 * 32 + lane];
        uint2 q3 = Ye2[(size_t)e3 * 32 + lane];
        float2 a0 = __half22float2(*reinterpret_cast<__half2*>(&q0.x));
        float2 b0 = __half22float2(*reinterpret_cast<__half2*>(&q0.y));
        float2 a1 = __half22float2(*reinterpret_cast<__half2*>(&q1.x));
        float2 b1 = __half22float2(*reinterpret_cast<__half2*>(&q1.y));
        float2 a2 = __half22float2(*reinterpret_cast<__half2*>(&q2.x));
        float2 b2 = __half22float2(*reinterpret_cast<__half2*>(&q2.y));
        float2 a3 = __half22float2(*reinterpret_cast<__half2*>(&q3.x));
        float2 b3 = __half22float2(*reinterpret_cast<__half2*>(&q3.y));
        sx += a0.x + a1.x + a2.x + a3.x;
        sy += a0.y + a1.y + a2.y + a3.y;
        sz += b0.x + b1.x + b2.x + b3.x;
        sw += b0.y + b1.y + b2.y + b3.y;
    }
    for (; j < end; j++) {
        int e = g_node_adj[j];
        uint2 q = Ye2[(size_t)e * 32 + lane];
        float2 a = __half22float2(*reinterpret_cast<__half2*>(&q.x));
        float2 b = __half22float2(*reinterpret_cast<__half2*>(&q.y));
        sx += a.x; sy += a.y; sz += b.x; sw += b.y;
    }
    float s = g_inv_sqrt_dv[gw];
    float4 o;
    o.x = fmaxf(sx * s, 0.f);
    o.y = fmaxf(sy * s, 0.f);
    o.z = fmaxf(sz * s, 0.f);
    o.w = fmaxf(sw * s, 0.f);
    ((float4*)out)[(size_t)gw * 32 + lane] = o;
}

// ---------------- launch ----------------
extern "C" void kernel_launch(void* const* d_in, const int* in_sizes, int n_in,
                              void* d_out, int out_size) {
    const float* X     = (const float*)d_in[0];
    const float* W     = (const float*)d_in[1];
    const float* bias  = (const float*)d_in[2];
    const int*   v_idx = (const int*)d_in[3];
    const int*   e_idx = (const int*)d_in[4];
    float* out = (float*)d_out;

    (void)in_sizes; (void)n_in; (void)out_size;

    cudaFuncSetAttribute(gemm_edges_kernel, cudaFuncAttributeMaxDynamicSharedMemorySize,
                         GEMM_SMEM_BYTES);

    int *cnt_e_p, *cnt_v_p, *offs_e_p, *offs_v_p, *part_v_p, *part_e_p;
    cudaGetSymbolAddress((void**)&cnt_e_p, g_cnt_e);
    cudaGetSymbolAddress((void**)&cnt_v_p, g_cnt_v);
    cudaGetSymbolAddress((void**)&offs_e_p, g_offs_e);
    cudaGetSymbolAddress((void**)&offs_v_p, g_offs_v);
    cudaGetSymbolAddress((void**)&part_v_p, g_part_v);
    cudaGetSymbolAddress((void**)&part_e_p, g_part_e);

    zero_counts_kernel<<<(N_NODES + 255) / 256, 256>>>();
    convert_X_kernel<<<(N_NODES * 32 + 255) / 256, 256>>>(X);
    degree_kernel<<<(NNZ + 255) / 256, 256>>>(v_idx, e_idx);

    const int NB_V = (N_NODES + 1023) / 1024;   // 98
    const int NB_E = (N_EDGES + 1023) / 1024;   // 20
    scanA_kernel<<<NB_V, 1024>>>(cnt_v_p, N_NODES, offs_v_p, part_v_p);
    scanA_kernel<<<NB_E, 1024>>>(cnt_e_p, N_EDGES, offs_e_p, part_e_p);
    scanB_kernel<<<1, 128>>>(part_v_p, NB_V, offs_v_p + N_NODES);
    scanB_kernel<<<1, 128>>>(part_e_p, NB_E, offs_e_p + N_EDGES);
    scanC_kernel<<<NB_V, 1024>>>(offs_v_p, N_NODES, part_v_p);
    scanC_kernel<<<NB_E, 1024>>>(offs_e_p, N_EDGES, part_e_p);

    init_kernel<<<(N_NODES + 255) / 256, 256>>>();
    fill_kernel<<<(NNZ + 255) / 256, 256>>>(v_idx, e_idx);

    edge_reduce_kernel<<<(N_EDGES * 32 + 255) / 256, 256>>>();
    gemm_edges_kernel<<<(N_EDGES + BM - 1) / BM, 256, GEMM_SMEM_BYTES>>>(W, bias);
    node_reduce_kernel<<<(N_NODES * 32 + 255) / 256, 256>>>(out);
}

// round 5
// speedup vs baseline: 1.8160x; 1.0588x over previous
#include <cuda_runtime.h>
#include <cuda_fp16.h>
#include <math.h>

#define N_NODES 100000
#define N_EDGES 20000
#define NNZ     1600000
#define D       128
#define NB_V    ((N_NODES + 1023) / 1024)   // 98
#define NB_E    ((N_EDGES + 1023) / 1024)   // 20

// ---------------- scratch (device globals: allocation-free rule) ----------------
__device__ int   g_cnt_v[N_NODES];
__device__ int   g_cnt_e[N_EDGES];
__device__ int   g_offs_v[N_NODES + 1];
__device__ int   g_offs_e[N_EDGES + 1];
__device__ int   g_pos[NNZ];                      // (pos_v << 16) | pos_e
__device__ int   g_part_v[128];
__device__ int   g_part_e[128];
__device__ float g_inv_sqrt_dv[N_NODES];
__device__ float g_inv_de[N_EDGES];
__device__ int   g_edge_adj[NNZ];                 // per-edge list of vertex ids
__device__ int   g_node_adj[NNZ];                 // per-node list of edge ids
__device__ unsigned g_Xh[(size_t)N_NODES * 64];   // X in half2 bit patterns
__device__ float g_Yp[(size_t)N_EDGES * D];       // inv_de * H^T Dv^-1/2 X (fp32)
__device__ float g_se[N_EDGES];                   // inv_de * H^T Dv^-1/2 1
__device__ unsigned g_Yeh[(size_t)N_EDGES * 64];  // Ye in half2

// ---------------- 1: zero counters + convert X -> half2 (fused) ----------------
__global__ void zero_convert_kernel(const float* __restrict__ X) {
    int i = blockIdx.x * blockDim.x + threadIdx.x;
    if (i < N_NODES) g_cnt_v[i] = 0;
    if (i < N_EDGES) g_cnt_e[i] = 0;
    if (i < N_NODES * 32) {
        float4 p = ((const float4*)X)[i];
        __half2 a = __floats2half2_rn(p.x, p.y);
        __half2 b = __floats2half2_rn(p.z, p.w);
        uint2 r;
        r.x = *reinterpret_cast<const unsigned*>(&a);
        r.y = *reinterpret_cast<const unsigned*>(&b);
        ((uint2*)g_Xh)[i] = r;
    }
}

// ---------------- 2: degree histograms + packed rank capture ----------------
__global__ void degree_kernel(const int* __restrict__ v_idx, const int* __restrict__ e_idx) {
    int i = blockIdx.x * blockDim.x + threadIdx.x;
    if (i < NNZ) {
        int pv = atomicAdd(&g_cnt_v[v_idx[i]], 1);
        int pe = atomicAdd(&g_cnt_e[e_idx[i]], 1);
        g_pos[i] = (pv << 16) | pe;
    }
}

// ---------------- 3: per-block scan of BOTH count arrays (one launch) ----------------
__device__ __forceinline__ void block_scan_1024(const int* in, int n, int base,
                                                int* out, int* partials, int pb) {
    __shared__ int wsum[32];
    int tid = threadIdx.x;
    int i = base + tid;
    int x = (i < n) ? in[i] : 0;
    int v = x;
    #pragma unroll
    for (int o = 1; o < 32; o <<= 1) {
        int t = __shfl_up_sync(0xFFFFFFFFu, v, o);
        if ((tid & 31) >= o) v += t;
    }
    if ((tid & 31) == 31) wsum[tid >> 5] = v;
    __syncthreads();
    if (tid < 32) {
        int w = wsum[tid];
        #pragma unroll
        for (int o = 1; o < 32; o <<= 1) {
            int t = __shfl_up_sync(0xFFFFFFFFu, w, o);
            if (tid >= o) w += t;
        }
        wsum[tid] = w;
    }
    __syncthreads();
    int warppre = (tid >= 32) ? wsum[(tid >> 5) - 1] : 0;
    int incl = v + warppre;
    if (i < n) out[i] = incl - x;
    if (tid == 1023) partials[pb] = incl;
}

__global__ void scanA_kernel() {
    int b = blockIdx.x;
    if (b < NB_V) block_scan_1024(g_cnt_v, N_NODES, b * 1024, g_offs_v, g_part_v, b);
    else { int eb = b - NB_V; block_scan_1024(g_cnt_e, N_EDGES, eb * 1024, g_offs_e, g_part_e, eb); }
}

// ---------------- 4: scan block sums for both (2 blocks) ----------------
__global__ void scanB_kernel() {
    __shared__ int wsum[4];
    int tid = threadIdx.x;                       // 128
    int* partials  = (blockIdx.x == 0) ? g_part_v : g_part_e;
    int  nblocks   = (blockIdx.x == 0) ? NB_V : NB_E;
    int* total_out = (blockIdx.x == 0) ? (g_offs_v + N_NODES) : (g_offs_e + N_EDGES);
    int x = (tid < nblocks) ? partials[tid] : 0;
    int v = x;
    #pragma unroll
    for (int o = 1; o < 32; o <<= 1) {
        int t = __shfl_up_sync(0xFFFFFFFFu, v, o);
        if ((tid & 31) >= o) v += t;
    }
    if ((tid & 31) == 31) wsum[tid >> 5] = v;
    __syncthreads();
    if (tid < 4) {
        int w = wsum[tid];
        #pragma unroll
        for (int o = 1; o < 4; o <<= 1) {
            int t = __shfl_up_sync(0xFu, w, o);
            if (tid >= o) w += t;
        }
        wsum[tid] = w;
    }
    __syncthreads();
    int warppre = (tid >= 32) ? wsum[(tid >> 5) - 1] : 0;
    int incl = v + warppre;
    if (tid < nblocks) partials[tid] = incl - x;
    if (tid == nblocks - 1) *total_out = incl;
}

// ---------------- 5: uniform add + inverse degree factors (fused, one launch) ----------------
__global__ void scanC_init_kernel() {
    int b = blockIdx.x;
    if (b < NB_V) {
        int i = b * 1024 + threadIdx.x;
        if (i < N_NODES) {
            g_offs_v[i] += g_part_v[b];
            int c = g_cnt_v[i];
            g_inv_sqrt_dv[i] = (c > 0) ? rsqrtf((float)c) : 0.0f;
        }
    } else {
        int i = (b - NB_V) * 1024 + threadIdx.x;
        if (i < N_EDGES) {
            g_offs_e[i] += g_part_e[b - NB_V];
            int c = g_cnt_e[i];
            g_inv_de[i] = (c > 0) ? (1.0f / (float)c) : 0.0f;
        }
    }
}

// ---------------- 6: CSR fill (atomic-free) ----------------
__global__ void fill_kernel(const int* __restrict__ v_idx, const int* __restrict__ e_idx) {
    int i = blockIdx.x * blockDim.x + threadIdx.x;
    if (i < NNZ) {
        int v = v_idx[i];
        int e = e_idx[i];
        int p = g_pos[i];
        g_edge_adj[g_offs_e[e] + (p & 0xFFFF)] = v;
        g_node_adj[g_offs_v[v] + (p >> 16)] = e;
    }
}

// ---------------- 7: edge gather-reduce (half2 X, 8-unrolled) ----------------
__global__ void edge_reduce_kernel() {
    int gw = (blockIdx.x * blockDim.x + threadIdx.x) >> 5;
    if (gw >= N_EDGES) return;
    int lane = threadIdx.x & 31;
    int beg = g_offs_e[gw], end = g_offs_e[gw + 1];
    const uint2* Xh2 = (const uint2*)g_Xh;
    float sx = 0.f, sy = 0.f, sz = 0.f, sw = 0.f, ssum = 0.f;
    int j = beg;
    for (; j + 8 <= end; j += 8) {
        int vv[8]; float sc[8]; uint2 q[8];
        #pragma unroll
        for (int u = 0; u < 8; u++) vv[u] = g_edge_adj[j + u];
        #pragma unroll
        for (int u = 0; u < 8; u++) sc[u] = g_inv_sqrt_dv[vv[u]];
        #pragma unroll
        for (int u = 0; u < 8; u++) q[u] = Xh2[(size_t)vv[u] * 32 + lane];
        #pragma unroll
        for (int u = 0; u < 8; u++) {
            float2 a = __half22float2(*reinterpret_cast<__half2*>(&q[u].x));
            float2 b = __half22float2(*reinterpret_cast<__half2*>(&q[u].y));
            sx = fmaf(sc[u], a.x, sx);
            sy = fmaf(sc[u], a.y, sy);
            sz = fmaf(sc[u], b.x, sz);
            sw = fmaf(sc[u], b.y, sw);
            ssum += sc[u];
        }
    }
    for (; j < end; j++) {
        int v = g_edge_adj[j];
        float s = g_inv_sqrt_dv[v];
        uint2 q = Xh2[(size_t)v * 32 + lane];
        float2 a = __half22float2(*reinterpret_cast<__half2*>(&q.x));
        float2 b = __half22float2(*reinterpret_cast<__half2*>(&q.y));
        sx = fmaf(s, a.x, sx);
        sy = fmaf(s, a.y, sy);
        sz = fmaf(s, b.x, sz);
        sw = fmaf(s, b.y, sw);
        ssum += s;
    }
    float s = g_inv_de[gw];
    ((float4*)g_Yp)[(size_t)gw * 32 + lane] = make_float4(sx * s, sy * s, sz * s, sw * s);
    if (lane == 0) g_se[gw] = ssum * s;
}

// ---------------- 8: small GEMM  Ye = Yp @ W + se * b  (fp32 math, half2 out) ----------------
#define BM 64
#define XS_STRIDE 132
#define GEMM_SMEM_BYTES ((128 * 128 + BM * XS_STRIDE + 128) * 4)

__global__ void __launch_bounds__(256)
gemm_edges_kernel(const float* __restrict__ W, const float* __restrict__ bias) {
    extern __shared__ float sm[];
    float* Wsm = sm;
    float* Ysm = sm + 128 * 128;
    float* bsm = Ysm + BM * XS_STRIDE;

    int tid = threadIdx.x;
    int row0 = blockIdx.x * BM;

    for (int i = tid; i < 128 * 32; i += 256)
        ((float4*)Wsm)[i] = ((const float4*)W)[i];
    if (tid < 32)
        ((float4*)bsm)[tid] = ((const float4*)bias)[tid];
    for (int i = tid; i < BM * 32; i += 256) {
        int m = i >> 5, kq = i & 31;
        int gr = row0 + m;
        float4 vv = (gr < N_EDGES) ? ((const float4*)(g_Yp + (size_t)gr * D))[kq]
                                   : make_float4(0.f, 0.f, 0.f, 0.f);
        *((float4*)(Ysm + m * XS_STRIDE + kq * 4)) = vv;
    }
    __syncthreads();

    int tx = tid & 31;
    int ty = tid >> 5;
    int c0 = tx * 4, r0 = ty * 8;

    float acc[8][4];
    #pragma unroll
    for (int j = 0; j < 8; j++) {
        acc[j][0] = 0.f; acc[j][1] = 0.f; acc[j][2] = 0.f; acc[j][3] = 0.f;
    }

    #pragma unroll 8
    for (int k = 0; k < 128; k++) {
        float4 b4 = *(const float4*)(Wsm + k * 128 + c0);
        #pragma unroll
        for (int j = 0; j < 8; j++) {
            float a = Ysm[(r0 + j) * XS_STRIDE + k];
            acc[j][0] = fmaf(a, b4.x, acc[j][0]);
            acc[j][1] = fmaf(a, b4.y, acc[j][1]);
            acc[j][2] = fmaf(a, b4.z, acc[j][2]);
            acc[j][3] = fmaf(a, b4.w, acc[j][3]);
        }
    }

    float4 bb = *(const float4*)(bsm + c0);
    #pragma unroll
    for (int j = 0; j < 8; j++) {
        int gr = row0 + r0 + j;
        if (gr < N_EDGES) {
            float se = g_se[gr];
            float ox = fmaf(se, bb.x, acc[j][0]);
            float oy = fmaf(se, bb.y, acc[j][1]);
            float oz = fmaf(se, bb.z, acc[j][2]);
            float ow = fmaf(se, bb.w, acc[j][3]);
            __half2 h0 = __floats2half2_rn(ox, oy);
            __half2 h1 = __floats2half2_rn(oz, ow);
            uint2 r;
            r.x = *reinterpret_cast<const unsigned*>(&h0);
            r.y = *reinterpret_cast<const unsigned*>(&h1);
            ((uint2*)g_Yeh)[(size_t)gr * 32 + tx] = r;
        }
    }
}

// ---------------- 9: node gather-reduce (half2 Ye, 8-unrolled) + relu ----------------
__global__ void node_reduce_kernel(float* __restrict__ out) {
    int gw = (blockIdx.x * blockDim.x + threadIdx.x) >> 5;
    if (gw >= N_NODES) return;
    int lane = threadIdx.x & 31;
    int beg = g_offs_v[gw], end = g_offs_v[gw + 1];
    const uint2* Ye2 = (const uint2*)g_Yeh;
    float sx = 0.f, sy = 0.f, sz = 0.f, sw = 0.f;
    int j = beg;
    for (; j + 8 <= end; j += 8) {
        int ee[8]; uint2 q[8];
        #pragma unroll
        for (int u = 0; u < 8; u++) ee[u] = g_node_adj[j + u];
        #pragma unroll
        for (int u = 0; u < 8; u++) q[u] = Ye2[(size_t)ee[u] * 32 + lane];
        #pragma unroll
        for (int u = 0; u < 8; u++) {
            float2 a = __half22float2(*reinterpret_cast<__half2*>(&q[u].x));
            float2 b = __half22float2(*reinterpret_cast<__half2*>(&q[u].y));
            sx += a.x; sy += a.y; sz += b.x; sw += b.y;
        }
    }
    for (; j < end; j++) {
        int e = g_node_adj[j];
        uint2 q = Ye2[(size_t)e * 32 + lane];
        float2 a = __half22float2(*reinterpret_cast<__half2*>(&q.x));
        float2 b = __half22float2(*reinterpret_cast<__half2*>(&q.y));
        sx += a.x; sy += a.y; sz += b.x; sw += b.y;
    }
    float s = g_inv_sqrt_dv[gw];
    float4 o;
    o.x = fmaxf(sx * s, 0.f);
    o.y = fmaxf(sy * s, 0.f);
    o.z = fmaxf(sz * s, 0.f);
    o.w = fmaxf(sw * s, 0.f);
    ((float4*)out)[(size_t)gw * 32 + lane] = o;
}

// ---------------- launch ----------------
extern "C" void kernel_launch(void* const* d_in, const int* in_sizes, int n_in,
                              void* d_out, int out_size) {
    const float* X     = (const float*)d_in[0];
    const float* W     = (const float*)d_in[1];
    const float* bias  = (const float*)d_in[2];
    const int*   v_idx = (const int*)d_in[3];
    const int*   e_idx = (const int*)d_in[4];
    float* out = (float*)d_out;

    (void)in_sizes; (void)n_in; (void)out_size;

    cudaFuncSetAttribute(gemm_edges_kernel, cudaFuncAttributeMaxDynamicSharedMemorySize,
                         GEMM_SMEM_BYTES);

    zero_convert_kernel<<<(N_NODES * 32 + 255) / 256, 256>>>(X);
    degree_kernel<<<(NNZ + 255) / 256, 256>>>(v_idx, e_idx);
    scanA_kernel<<<NB_V + NB_E, 1024>>>();
    scanB_kernel<<<2, 128>>>();
    scanC_init_kernel<<<NB_V + NB_E, 1024>>>();
    fill_kernel<<<(NNZ + 255) / 256, 256>>>(v_idx, e_idx);
    edge_reduce_kernel<<<(N_EDGES * 32 + 255) / 256, 256>>>();
    gemm_edges_kernel<<<(N_EDGES + BM - 1) / BM, 256, GEMM_SMEM_BYTES>>>(W, bias);
    node_reduce_kernel<<<(N_NODES * 32 + 255) / 256, 256>>>(out);
}

// round 6
// speedup vs baseline: 1.8827x; 1.0367x over previous
#include <cuda_runtime.h>
#include <cuda_fp16.h>
#include <math.h>

#define N_NODES 100000
#define N_EDGES 20000
#define NNZ     1600000
#define D       128
#define NB_V    ((N_NODES + 1023) / 1024)   // 98
#define NB_E    ((N_EDGES + 1023) / 1024)   // 20

// ---------------- scratch (device globals: allocation-free rule) ----------------
// Invariant maintained across executions: g_cnt_v/g_cnt_e/g_state_v/g_state_e are
// ZERO at kernel_launch entry (statically zero-initialized; re-zeroed by
// fill_kernel after their last use each execution). Deterministic every call.
__device__ int   g_cnt_v[N_NODES];
__device__ int   g_cnt_e[N_EDGES];
__device__ unsigned long long g_state_v[NB_V];    // lookback: (value<<2)|flag
__device__ unsigned long long g_state_e[NB_E];
__device__ int   g_offs_v[N_NODES + 1];
__device__ int   g_offs_e[N_EDGES + 1];
__device__ int   g_pos[NNZ];                      // (pos_v << 16) | pos_e
__device__ float g_inv_sqrt_dv[N_NODES];
__device__ float g_inv_de[N_EDGES];
__device__ int   g_edge_adj[NNZ];                 // per-edge list of vertex ids
__device__ int   g_node_adj[NNZ];                 // per-node list of edge ids
__device__ unsigned g_Xh[(size_t)N_NODES * 64];   // X in half2 bit patterns
__device__ float g_Yp[(size_t)N_EDGES * D];       // inv_de * H^T Dv^-1/2 X (fp32)
__device__ float g_se[N_EDGES];                   // inv_de * H^T Dv^-1/2 1
__device__ unsigned g_Yeh[(size_t)N_EDGES * 64];  // Ye in half2

// ---------------- 1: degree histograms + rank capture + X->half2 convert ----------------
__global__ void degree_convert_kernel(const float* __restrict__ X,
                                      const int* __restrict__ v_idx,
                                      const int* __restrict__ e_idx) {
    int i = blockIdx.x * blockDim.x + threadIdx.x;   // grid covers N_NODES*32
    if (i < N_NODES * 32) {
        float4 p = ((const float4*)X)[i];
        __half2 a = __floats2half2_rn(p.x, p.y);
        __half2 b = __floats2half2_rn(p.z, p.w);
        uint2 r;
        r.x = *reinterpret_cast<const unsigned*>(&a);
        r.y = *reinterpret_cast<const unsigned*>(&b);
        ((uint2*)g_Xh)[i] = r;
    }
    if (i < NNZ) {
        int pv = atomicAdd(&g_cnt_v[v_idx[i]], 1);
        int pe = atomicAdd(&g_cnt_e[e_idx[i]], 1);
        g_pos[i] = (pv << 16) | pe;
    }
}

// ---------------- 2: single-pass decoupled-lookback scan (both arrays) + inv factors ----------------
__global__ void scan_fused_kernel() {
    __shared__ int wsum[32];
    __shared__ int s_agg;
    __shared__ int s_prefix;
    int tid = threadIdx.x;                        // 1024
    int b = blockIdx.x;
    int chain_e = (b >= NB_V);
    int pb = chain_e ? (b - NB_V) : b;            // chain-local block index
    const int* in   = chain_e ? g_cnt_e : g_cnt_v;
    int*       out  = chain_e ? g_offs_e : g_offs_v;
    int        n    = chain_e ? N_EDGES : N_NODES;
    unsigned long long* st = chain_e ? g_state_e : g_state_v;

    int i = pb * 1024 + tid;
    int x = (i < n) ? in[i] : 0;

    // inverse degree factors, straight from the count
    if (i < n) {
        if (chain_e) g_inv_de[i] = (x > 0) ? (1.0f / (float)x) : 0.0f;
        else         g_inv_sqrt_dv[i] = (x > 0) ? rsqrtf((float)x) : 0.0f;
    }

    // block-local inclusive scan
    int v = x;
    #pragma unroll
    for (int o = 1; o < 32; o <<= 1) {
        int t = __shfl_up_sync(0xFFFFFFFFu, v, o);
        if ((tid & 31) >= o) v += t;
    }
    if ((tid & 31) == 31) wsum[tid >> 5] = v;
    __syncthreads();
    if (tid < 32) {
        int w = wsum[tid];
        #pragma unroll
        for (int o = 1; o < 32; o <<= 1) {
            int t = __shfl_up_sync(0xFFFFFFFFu, w, o);
            if (tid >= o) w += t;
        }
        wsum[tid] = w;
    }
    __syncthreads();
    int warppre = (tid >= 32) ? wsum[(tid >> 5) - 1] : 0;
    int incl = v + warppre;
    if (tid == 1023) s_agg = incl;
    __syncthreads();

    // publish aggregate, then warp-parallel lookback (warp 0)
    if (tid < 32) {
        int agg = s_agg;
        int run = 0;
        if (pb == 0) {
            if (tid == 0) atomicExch(&st[0], ((unsigned long long)agg << 2) | 2ULL);
        } else {
            if (tid == 0) atomicExch(&st[pb], ((unsigned long long)agg << 2) | 1ULL);
            __syncwarp();
            int p = pb - 1;
            while (true) {
                int idx = p - (int)tid;
                int flag;
                int val = 0;
                if (idx >= 0) {
                    unsigned long long s;
                    do { s = atomicAdd(&st[idx], 0ULL); flag = (int)(s & 3ULL); } while (flag == 0);
                    val = (int)(s >> 2);
                } else {
                    flag = 2;           // past block 0: contributes nothing, stops the walk
                }
                unsigned m2 = __ballot_sync(0xFFFFFFFFu, flag == 2);
                int k = __ffs(m2) - 1;  // first (closest) prefix lane, -1 if none
                int contrib = (m2 == 0u || (int)tid <= k) ? val : 0;
                #pragma unroll
                for (int o = 16; o; o >>= 1) contrib += __shfl_down_sync(0xFFFFFFFFu, contrib, o);
                contrib = __shfl_sync(0xFFFFFFFFu, contrib, 0);
                run += contrib;
                if (m2) break;
                p -= 32;
            }
            if (tid == 0) atomicExch(&st[pb], ((unsigned long long)(agg + run) << 2) | 2ULL);
        }
        if (tid == 0) s_prefix = run;
    }
    __syncthreads();

    if (i < n) out[i] = s_prefix + incl - x;      // global exclusive prefix
    if (b == 0 && tid == 0) {                     // totals are NNZ by construction
        g_offs_v[N_NODES] = NNZ;
        g_offs_e[N_EDGES] = NNZ;
    }
}

// ---------------- 3: CSR fill (atomic-free) + re-zero counters/states for next exec ----------------
__global__ void fill_kernel(const int* __restrict__ v_idx, const int* __restrict__ e_idx) {
    int i = blockIdx.x * blockDim.x + threadIdx.x;   // grid covers NNZ
    if (i < NNZ) {
        int v = v_idx[i];
        int e = e_idx[i];
        int p = g_pos[i];
        g_edge_adj[g_offs_e[e] + (p & 0xFFFF)] = v;
        g_node_adj[g_offs_v[v] + (p >> 16)] = e;
    }
    // last use of counters/states was scan_fused_kernel -> safe to re-zero here
    if (i < N_NODES) g_cnt_v[i] = 0;
    if (i < N_EDGES) g_cnt_e[i] = 0;
    if (i < NB_V) g_state_v[i] = 0ULL;
    if (i < NB_E) g_state_e[i] = 0ULL;
}

// ---------------- 4: edge gather-reduce (half2 X, 8-unrolled) ----------------
__global__ void edge_reduce_kernel() {
    int gw = (blockIdx.x * blockDim.x + threadIdx.x) >> 5;
    if (gw >= N_EDGES) return;
    int lane = threadIdx.x & 31;
    int beg = g_offs_e[gw], end = g_offs_e[gw + 1];
    const uint2* Xh2 = (const uint2*)g_Xh;
    float sx = 0.f, sy = 0.f, sz = 0.f, sw = 0.f, ssum = 0.f;
    int j = beg;
    for (; j + 8 <= end; j += 8) {
        int vv[8]; float sc[8]; uint2 q[8];
        #pragma unroll
        for (int u = 0; u < 8; u++) vv[u] = g_edge_adj[j + u];
        #pragma unroll
        for (int u = 0; u < 8; u++) sc[u] = g_inv_sqrt_dv[vv[u]];
        #pragma unroll
        for (int u = 0; u < 8; u++) q[u] = Xh2[(size_t)vv[u] * 32 + lane];
        #pragma unroll
        for (int u = 0; u < 8; u++) {
            float2 a = __half22float2(*reinterpret_cast<__half2*>(&q[u].x));
            float2 b = __half22float2(*reinterpret_cast<__half2*>(&q[u].y));
            sx = fmaf(sc[u], a.x, sx);
            sy = fmaf(sc[u], a.y, sy);
            sz = fmaf(sc[u], b.x, sz);
            sw = fmaf(sc[u], b.y, sw);
            ssum += sc[u];
        }
    }
    for (; j < end; j++) {
        int v = g_edge_adj[j];
        float s = g_inv_sqrt_dv[v];
        uint2 q = Xh2[(size_t)v * 32 + lane];
        float2 a = __half22float2(*reinterpret_cast<__half2*>(&q.x));
        float2 b = __half22float2(*reinterpret_cast<__half2*>(&q.y));
        sx = fmaf(s, a.x, sx);
        sy = fmaf(s, a.y, sy);
        sz = fmaf(s, b.x, sz);
        sw = fmaf(s, b.y, sw);
        ssum += s;
    }
    float s = g_inv_de[gw];
    ((float4*)g_Yp)[(size_t)gw * 32 + lane] = make_float4(sx * s, sy * s, sz * s, sw * s);
    if (lane == 0) g_se[gw] = ssum * s;
}

// ---------------- 5: small GEMM  Ye = Yp @ W + se * b  (fp32 math, half2 out) ----------------
#define BM 64
#define XS_STRIDE 132
#define GEMM_SMEM_BYTES ((128 * 128 + BM * XS_STRIDE + 128) * 4)

__global__ void __launch_bounds__(256)
gemm_edges_kernel(const float* __restrict__ W, const float* __restrict__ bias) {
    extern __shared__ float sm[];
    float* Wsm = sm;
    float* Ysm = sm + 128 * 128;
    float* bsm = Ysm + BM * XS_STRIDE;

    int tid = threadIdx.x;
    int row0 = blockIdx.x * BM;

    for (int i = tid; i < 128 * 32; i += 256)
        ((float4*)Wsm)[i] = ((const float4*)W)[i];
    if (tid < 32)
        ((float4*)bsm)[tid] = ((const float4*)bias)[tid];
    for (int i = tid; i < BM * 32; i += 256) {
        int m = i >> 5, kq = i & 31;
        int gr = row0 + m;
        float4 vv = (gr < N_EDGES) ? ((const float4*)(g_Yp + (size_t)gr * D))[kq]
                                   : make_float4(0.f, 0.f, 0.f, 0.f);
        *((float4*)(Ysm + m * XS_STRIDE + kq * 4)) = vv;
    }
    __syncthreads();

    int tx = tid & 31;
    int ty = tid >> 5;
    int c0 = tx * 4, r0 = ty * 8;

    float acc[8][4];
    #pragma unroll
    for (int j = 0; j < 8; j++) {
        acc[j][0] = 0.f; acc[j][1] = 0.f; acc[j][2] = 0.f; acc[j][3] = 0.f;
    }

    #pragma unroll 8
    for (int k = 0; k < 128; k++) {
        float4 b4 = *(const float4*)(Wsm + k * 128 + c0);
        #pragma unroll
        for (int j = 0; j < 8; j++) {
            float a = Ysm[(r0 + j) * XS_STRIDE + k];
            acc[j][0] = fmaf(a, b4.x, acc[j][0]);
            acc[j][1] = fmaf(a, b4.y, acc[j][1]);
            acc[j][2] = fmaf(a, b4.z, acc[j][2]);
            acc[j][3] = fmaf(a, b4.w, acc[j][3]);
        }
    }

    float4 bb = *(const float4*)(bsm + c0);
    #pragma unroll
    for (int j = 0; j < 8; j++) {
        int gr = row0 + r0 + j;
        if (gr < N_EDGES) {
            float se = g_se[gr];
            float ox = fmaf(se, bb.x, acc[j][0]);
            float oy = fmaf(se, bb.y, acc[j][1]);
            float oz = fmaf(se, bb.z, acc[j][2]);
            float ow = fmaf(se, bb.w, acc[j][3]);
            __half2 h0 = __floats2half2_rn(ox, oy);
            __half2 h1 = __floats2half2_rn(oz, ow);
            uint2 r;
            r.x = *reinterpret_cast<const unsigned*>(&h0);
            r.y = *reinterpret_cast<const unsigned*>(&h1);
            ((uint2*)g_Yeh)[(size_t)gr * 32 + tx] = r;
        }
    }
}

// ---------------- 6: node gather-reduce (half2 Ye, 8-unrolled) + relu ----------------
__global__ void node_reduce_kernel(float* __restrict__ out) {
    int gw = (blockIdx.x * blockDim.x + threadIdx.x) >> 5;
    if (gw >= N_NODES) return;
    int lane = threadIdx.x & 31;
    int beg = g_offs_v[gw], end = g_offs_v[gw + 1];
    const uint2* Ye2 = (const uint2*)g_Yeh;
    float sx = 0.f, sy = 0.f, sz = 0.f, sw = 0.f;
    int j = beg;
    for (; j + 8 <= end; j += 8) {
        int ee[8]; uint2 q[8];
        #pragma unroll
        for (int u = 0; u < 8; u++) ee[u] = g_node_adj[j + u];
        #pragma unroll
        for (int u = 0; u < 8; u++) q[u] = Ye2[(size_t)ee[u] * 32 + lane];
        #pragma unroll
        for (int u = 0; u < 8; u++) {
            float2 a = __half22float2(*reinterpret_cast<__half2*>(&q[u].x));
            float2 b = __half22float2(*reinterpret_cast<__half2*>(&q[u].y));
            sx += a.x; sy += a.y; sz += b.x; sw += b.y;
        }
    }
    for (; j < end; j++) {
        int e = g_node_adj[j];
        uint2 q = Ye2[(size_t)e * 32 + lane];
        float2 a = __half22float2(*reinterpret_cast<__half2*>(&q.x));
        float2 b = __half22float2(*reinterpret_cast<__half2*>(&q.y));
        sx += a.x; sy += a.y; sz += b.x; sw += b.y;
    }
    float s = g_inv_sqrt_dv[gw];
    float4 o;
    o.x = fmaxf(sx * s, 0.f);
    o.y = fmaxf(sy * s, 0.f);
    o.z = fmaxf(sz * s, 0.f);
    o.w = fmaxf(sw * s, 0.f);
    ((float4*)out)[(size_t)gw * 32 + lane] = o;
}

// ---------------- launch ----------------
extern "C" void kernel_launch(void* const* d_in, const int* in_sizes, int n_in,
                              void* d_out, int out_size) {
    const float* X     = (const float*)d_in[0];
    const float* W     = (const float*)d_in[1];
    const float* bias  = (const float*)d_in[2];
    const int*   v_idx = (const int*)d_in[3];
    const int*   e_idx = (const int*)d_in[4];
    float* out = (float*)d_out;

    (void)in_sizes; (void)n_in; (void)out_size;

    cudaFuncSetAttribute(gemm_edges_kernel, cudaFuncAttributeMaxDynamicSharedMemorySize,
                         GEMM_SMEM_BYTES);

    degree_convert_kernel<<<(N_NODES * 32 + 255) / 256, 256>>>(X, v_idx, e_idx);
    scan_fused_kernel<<<NB_V + NB_E, 1024>>>();
    fill_kernel<<<(NNZ + 255) / 256, 256>>>(v_idx, e_idx);
    edge_reduce_kernel<<<(N_EDGES * 32 + 255) / 256, 256>>>();
    gemm_edges_kernel<<<(N_EDGES + BM - 1) / BM, 256, GEMM_SMEM_BYTES>>>(W, bias);
    node_reduce_kernel<<<(N_NODES * 32 + 255) / 256, 256>>>(out);
}